// round 11
// baseline (speedup 1.0000x reference)
#include <cuda_runtime.h>

#define IMG      512
#define TW       64
#define STRIPH   128
#define CHUNK    32
#define HB       42          // smem buffer rows
#define HSTRIDE  66          // 528B row stride, 16B-aligned float4 stores
#define NT       256
#define NPLANES  192
#define NBLOCKS  (8 * 4 * 192)
#define NPIX     (64.0 * 3.0 * 512.0 * 512.0)

typedef unsigned long long u64;

__device__ constexpr float GW[6] = {
    1.0283886e-3f, 7.5988485e-3f, 3.6000773e-2f, 1.0936073e-1f, 2.1300553e-1f,
    2.6601180e-1f
};

#define C1X2 8.0e-4f     // 2*C1
#define C2X2 7.2e-3f     // 2*C2

__device__ double g_acc[2];
__device__ unsigned int g_count;

// ---------- packed f32x2 helpers ----------
__device__ __forceinline__ u64 pk2(float lo, float hi) {
    u64 r; asm("mov.b64 %0,{%1,%2};" : "=l"(r) : "f"(lo), "f"(hi)); return r;
}
__device__ __forceinline__ void upk(u64 a, float& lo, float& hi) {
    asm("mov.b64 {%0,%1},%2;" : "=f"(lo), "=f"(hi) : "l"(a));
}
__device__ __forceinline__ u64 f2fma(u64 a, u64 b, u64 c) {
    u64 d; asm("fma.rn.f32x2 %0,%1,%2,%3;" : "=l"(d) : "l"(a), "l"(b), "l"(c)); return d;
}
__device__ __forceinline__ u64 f2add(u64 a, u64 b) {
    u64 d; asm("add.rn.f32x2 %0,%1,%2;" : "=l"(d) : "l"(a), "l"(b)); return d;
}
__device__ __forceinline__ u64 f2mul(u64 a, u64 b) {
    u64 d; asm("mul.rn.f32x2 %0,%1,%2;" : "=l"(d) : "l"(a), "l"(b)); return d;
}

// 11-tap symmetric conv on packed pairs
__device__ __forceinline__ u64 conv11(const u64* w, const u64* G2) {
    u64 acc = f2mul(G2[5], w[5]);
#pragma unroll
    for (int k = 0; k < 5; k++)
        acc = f2fma(G2[k], f2add(w[k], w[10 - k]), acc);
    return acc;
}

// ---------------- Phase A producer: nrows H-rows into buffer ----------------
// COLG: column guards. ROWG: image-row guards. MSE for local rows [mlo,mhi).
template <bool COLG, bool ROWG>
__device__ __forceinline__ u64 produceRows(
    const float* __restrict__ xp, const float* __restrict__ yp,
    int col0, int tid, int hb0, int rimg0, int nrows, int mlo, int mhi,
    u64 (*Hsd)[HSTRIDE], u64 (*Huv)[HSTRIDE], const u64* G2)
{
    u64 msep = 0;
    for (int s = tid; s < (nrows << 4); s += NT) {
        const int rr = s >> 4;
        const int q  = s & 15;
        const int hb = hb0 + rr;
        const int rimg = rimg0 + rr;
        const int cb   = col0 + q * 4 - 8;   // 16B aligned

        u64 wsd[14];
        bool rok = true, vec = true;
        if (ROWG) { rok = ((unsigned)rimg < IMG); vec = rok; }
        if (COLG) vec = vec && (cb >= 0) && (cb + 20 <= IMG);

        if (vec) {
            const float4* xr = reinterpret_cast<const float4*>(xp + (size_t)rimg * IMG + cb);
            const float4* yr = reinterpret_cast<const float4*>(yp + (size_t)rimg * IMG + cb);
#pragma unroll
            for (int v = 0; v < 5; v++) {
                const float4 fx = __ldg(xr + v);
                const float4 fy = __ldg(yr + v);
                const float xe[4] = { fx.x, fx.y, fx.z, fx.w };
                const float ye[4] = { fy.x, fy.y, fy.z, fy.w };
#pragma unroll
                for (int e = 0; e < 4; e++) {
                    const int i = 4 * v + e;       // col cb+i; window i in [3,17)
                    if (i >= 3 && i < 17)
                        wsd[i - 3] = pk2(xe[e] + ye[e], xe[e] - ye[e]);
                }
            }
        } else if (COLG && rok) {
#pragma unroll
            for (int m = 0; m < 14; m++) {
                const int c = cb + 3 + m;
                float xv = 0.f, yv = 0.f;
                if ((unsigned)c < IMG) {
                    xv = __ldg(xp + (size_t)rimg * IMG + c);
                    yv = __ldg(yp + (size_t)rimg * IMG + c);
                }
                wsd[m] = pk2(xv + yv, xv - yv);
            }
        } else {
#pragma unroll
            for (int m = 0; m < 14; m++) wsd[m] = 0;
        }

        // MSE: owned local rows only (hi lane of wsd = D)
        if (rr >= mlo && rr < mhi) {
#pragma unroll
            for (int m = 5; m < 9; m++) msep = f2fma(wsd[m], wsd[m], msep);
        }

        // SD conv + store (raw u64 pair stores; 16B-aligned)
        {
            const u64 o0 = conv11(wsd + 0, G2), o1 = conv11(wsd + 1, G2);
            const u64 o2 = conv11(wsd + 2, G2), o3 = conv11(wsd + 3, G2);
            ulonglong2* p = reinterpret_cast<ulonglong2*>(&Hsd[hb][q * 4]);
            p[0] = make_ulonglong2(o0, o1);
            p[1] = make_ulonglong2(o2, o3);
        }
        // square in place, UV conv + store
#pragma unroll
        for (int m = 0; m < 14; m++) wsd[m] = f2mul(wsd[m], wsd[m]);
        {
            const u64 o0 = conv11(wsd + 0, G2), o1 = conv11(wsd + 1, G2);
            const u64 o2 = conv11(wsd + 2, G2), o3 = conv11(wsd + 3, G2);
            ulonglong2* p = reinterpret_cast<ulonglong2*>(&Huv[hb][q * 4]);
            p[0] = make_ulonglong2(o0, o1);
            p[1] = make_ulonglong2(o2, o3);
        }
    }
    return msep;
}

__device__ __forceinline__ u64 produceDispatch(
    bool colg, bool rowg,
    const float* __restrict__ xp, const float* __restrict__ yp,
    int col0, int tid, int hb0, int rimg0, int nrows, int mlo, int mhi,
    u64 (*Hsd)[HSTRIDE], u64 (*Huv)[HSTRIDE], const u64* G2)
{
    if (colg) {
        if (rowg) return produceRows<true , true >(xp, yp, col0, tid, hb0, rimg0, nrows, mlo, mhi, Hsd, Huv, G2);
        else      return produceRows<true , false>(xp, yp, col0, tid, hb0, rimg0, nrows, mlo, mhi, Hsd, Huv, G2);
    } else {
        if (rowg) return produceRows<false, true >(xp, yp, col0, tid, hb0, rimg0, nrows, mlo, mhi, Hsd, Huv, G2);
        else      return produceRows<false, false>(xp, yp, col0, tid, hb0, rimg0, nrows, mlo, mhi, Hsd, Huv, G2);
    }
}

// ---------------- Phase B consumer: one 64x32 chunk ----------------
__device__ __forceinline__ float consumeChunk(
    int tid, u64 (*Hsd)[HSTRIDE], u64 (*Huv)[HSTRIDE], const u64* G2, u64 MM1)
{
    const int col   = tid & 63;
    const int strip = tid >> 6;
    const int rb    = strip * 8;

    u64 ring[11];
    u64 vsd[8];

    // pass 1: SD stream
#pragma unroll
    for (int k = 0; k < 10; k++) ring[k] = Hsd[rb + k][col];
#pragma unroll
    for (int r = 0; r < 8; r++) {
        ring[(r + 10) % 11] = Hsd[rb + r + 10][col];
        u64 acc = f2mul(G2[5], ring[(r + 5) % 11]);
#pragma unroll
        for (int k = 0; k < 5; k++)
            acc = f2fma(G2[k], f2add(ring[(r + k) % 11], ring[(r + 10 - k) % 11]), acc);
        vsd[r] = acc;
    }

    // pass 2: UV stream + epilogue (x4-scaled: ratio unchanged)
    float ssim_acc = 0.f;
#pragma unroll
    for (int k = 0; k < 10; k++) ring[k] = Huv[rb + k][col];
#pragma unroll
    for (int r = 0; r < 8; r++) {
        ring[(r + 10) % 11] = Huv[rb + r + 10][col];
        u64 acc = f2mul(G2[5], ring[(r + 5) % 11]);
#pragma unroll
        for (int k = 0; k < 5; k++)
            acc = f2fma(G2[k], f2add(ring[(r + k) % 11], ring[(r + 10 - k) % 11]), acc);

        const u64 s2d2 = f2mul(vsd[r], vsd[r]);          // (S^2, D^2)
        const u64 varp = f2fma(s2d2, MM1, acc);          // (varS, varD)
        float S2, D2, varS, varD;
        upk(s2d2, S2, D2);
        upk(varp, varS, varD);
        const float Ap = S2 - D2;            // 4*mu1*mu2
        const float Mp = S2 + D2;            // 2*(mu1^2+mu2^2)
        const float cd = varS - varD;        // 4*sigma12
        const float cs = varS + varD;        // 2*(sigma1^2+sigma2^2)
        const float num = (Ap + C1X2) * (cd + C2X2);
        const float den = (Mp + C1X2) * (cs + C2X2);
        ssim_acc += __fdividef(num, den);
    }
    return ssim_acc;
}

__global__ void __launch_bounds__(NT, 4) ssim_mse_kernel(
    const float* __restrict__ x, const float* __restrict__ y,
    float* __restrict__ out)
{
    __shared__ alignas(16) u64 Hsd[HB][HSTRIDE];
    __shared__ alignas(16) u64 Huv[HB][HSTRIDE];
    __shared__ float red_m[8], red_s[8];

    const int plane = blockIdx.z;
    const int row0  = blockIdx.y * STRIPH;
    const int col0  = blockIdx.x * TW;
    const float* xp = x + (size_t)plane * (IMG * IMG);
    const float* yp = y + (size_t)plane * (IMG * IMG);
    const int tid = threadIdx.x;

    const u64 G2[6] = { pk2(GW[0], GW[0]), pk2(GW[1], GW[1]), pk2(GW[2], GW[2]),
                        pk2(GW[3], GW[3]), pk2(GW[4], GW[4]), pk2(GW[5], GW[5]) };
    const u64 MM1 = pk2(-1.0f, -1.0f);

    const bool colg = (blockIdx.x == 0) || (blockIdx.x == 7);

    u64 msep = 0;
    float ssim_acc = 0.f;

    // chunk 0: fill all 42 buffer rows (image rows row0-5 .. row0+36)
    msep = produceDispatch(colg, blockIdx.y == 0,
                           xp, yp, col0, tid, 0, row0 - 5, HB, 5, HB,
                           Hsd, Huv, G2);
    __syncthreads();
    ssim_acc += consumeChunk(tid, Hsd, Huv, G2, MM1);

#pragma unroll
    for (int c = 1; c < STRIPH / CHUNK; c++) {
        __syncthreads();                       // consume done before copy
        // slide buffer: rows 32..41 -> 0..9 (16B copies)
        for (int i = tid; i < 640; i += NT) {
            if (i < 320) {
                const int rw = i >> 5, c2 = (i & 31) * 2;
                *reinterpret_cast<ulonglong2*>(&Hsd[rw][c2]) =
                    *reinterpret_cast<const ulonglong2*>(&Hsd[rw + 32][c2]);
            } else {
                const int j = i - 320;
                const int rw = j >> 5, c2 = (j & 31) * 2;
                *reinterpret_cast<ulonglong2*>(&Huv[rw][c2]) =
                    *reinterpret_cast<const ulonglong2*>(&Huv[rw + 32][c2]);
            }
        }
        __syncthreads();                       // copy done before produce overwrites
        const bool rowg = (c == 3) && (blockIdx.y == 3);
        const int  mhi  = (c == 3) ? 27 : 32;
        msep = f2add(msep,
            produceDispatch(colg, rowg,
                            xp, yp, col0, tid, 10, row0 + 32 * c + 5, CHUNK, 0, mhi,
                            Hsd, Huv, G2));
        __syncthreads();                       // produce done before consume
        ssim_acc += consumeChunk(tid, Hsd, Huv, G2, MM1);
    }

    float mse_lo, mse_acc;
    upk(msep, mse_lo, mse_acc);                // hi lane = sum D^2

    // ---------------- Reduction + fused finalize ----------------
#pragma unroll
    for (int o = 16; o > 0; o >>= 1) {
        mse_acc  += __shfl_down_sync(0xffffffffu, mse_acc,  o);
        ssim_acc += __shfl_down_sync(0xffffffffu, ssim_acc, o);
    }
    const int wid = tid >> 5;
    if ((tid & 31) == 0) { red_m[wid] = mse_acc; red_s[wid] = ssim_acc; }
    __syncthreads();
    if (tid < 32) {
        float m  = (tid < 8) ? red_m[tid] : 0.f;
        float ss = (tid < 8) ? red_s[tid] : 0.f;
#pragma unroll
        for (int o = 4; o > 0; o >>= 1) {
            m  += __shfl_down_sync(0xffffffffu, m,  o);
            ss += __shfl_down_sync(0xffffffffu, ss, o);
        }
        if (tid == 0) {
            atomicAdd(&g_acc[0], (double)m);
            atomicAdd(&g_acc[1], (double)ss);
            __threadfence();
            const unsigned c = atomicAdd(&g_count, 1u);
            if (c == NBLOCKS - 1) {
                __threadfence();
                const double mse  = g_acc[0] / NPIX;
                const double ssim = g_acc[1] / NPIX;
                out[0] = (float)(0.7 * mse + 0.3 * (1.0 - ssim));
                g_acc[0] = 0.0;
                g_acc[1] = 0.0;
                __threadfence();
                g_count = 0u;
            }
        }
    }
}

extern "C" void kernel_launch(void* const* d_in, const int* in_sizes, int n_in,
                              void* d_out, int out_size)
{
    const float* recon = (const float*)d_in[0];
    const float* orig  = (const float*)d_in[1];
    float* out = (float*)d_out;

    dim3 grid(IMG / TW, IMG / STRIPH, NPLANES);   // 8 x 4 x 192 = 6144 blocks
    ssim_mse_kernel<<<grid, NT>>>(recon, orig, out);
}

// round 12
// speedup vs baseline: 1.0210x; 1.0210x over previous
#include <cuda_runtime.h>

#define IMG      512
#define TW       64
#define STRIPH   128
#define CHUNK    32
#define HB       42          // smem buffer rows
#define HSTRIDE  66          // 528B row stride, 16B-aligned float4 stores
#define NT       256
#define NPLANES  192
#define NBLOCKS  (8 * 4 * 192)
#define NPIX     (64.0 * 3.0 * 512.0 * 512.0)

typedef unsigned long long u64;

__device__ constexpr float GW[6] = {
    1.0283886e-3f, 7.5988485e-3f, 3.6000773e-2f, 1.0936073e-1f, 2.1300553e-1f,
    2.6601180e-1f
};

#define C1X2 8.0e-4f     // 2*C1
#define C2X2 7.2e-3f     // 2*C2

__device__ double g_acc[2];
__device__ unsigned int g_count;

// ---------- packed f32x2 helpers ----------
__device__ __forceinline__ u64 pk2(float lo, float hi) {
    u64 r; asm("mov.b64 %0,{%1,%2};" : "=l"(r) : "f"(lo), "f"(hi)); return r;
}
__device__ __forceinline__ void upk(u64 a, float& lo, float& hi) {
    asm("mov.b64 {%0,%1},%2;" : "=f"(lo), "=f"(hi) : "l"(a));
}
__device__ __forceinline__ u64 f2fma(u64 a, u64 b, u64 c) {
    u64 d; asm("fma.rn.f32x2 %0,%1,%2,%3;" : "=l"(d) : "l"(a), "l"(b), "l"(c)); return d;
}
__device__ __forceinline__ u64 f2add(u64 a, u64 b) {
    u64 d; asm("add.rn.f32x2 %0,%1,%2;" : "=l"(d) : "l"(a), "l"(b)); return d;
}
__device__ __forceinline__ u64 f2mul(u64 a, u64 b) {
    u64 d; asm("mul.rn.f32x2 %0,%1,%2;" : "=l"(d) : "l"(a), "l"(b)); return d;
}

// 11-tap symmetric conv on packed pairs
__device__ __forceinline__ u64 conv11(const u64* w, const u64* G2) {
    u64 acc = f2mul(G2[5], w[5]);
#pragma unroll
    for (int k = 0; k < 5; k++)
        acc = f2fma(G2[k], f2add(w[k], w[10 - k]), acc);
    return acc;
}

// ---------------- Phase A producer: nrows H-rows into buffer ----------------
// COLG: column guards. ROWG: image-row guards. MSE for local rows [mlo,mhi).
template <bool COLG, bool ROWG>
__device__ __forceinline__ u64 produceRows(
    const float* __restrict__ xp, const float* __restrict__ yp,
    int col0, int tid, int hb0, int rimg0, int nrows, int mlo, int mhi,
    u64 (*Hsd)[HSTRIDE], u64 (*Huv)[HSTRIDE], const u64* G2)
{
    u64 msep = 0;
    for (int s = tid; s < (nrows << 4); s += NT) {
        const int rr = s >> 4;
        const int q  = s & 15;
        const int hb = hb0 + rr;
        const int rimg = rimg0 + rr;
        const int cb   = col0 + q * 4 - 8;   // 16B aligned

        u64 wsd[14];
        bool rok = true, vec = true;
        if (ROWG) { rok = ((unsigned)rimg < IMG); vec = rok; }
        if (COLG) vec = vec && (cb >= 0) && (cb + 20 <= IMG);

        if (vec) {
            const float4* xr = reinterpret_cast<const float4*>(xp + (size_t)rimg * IMG + cb);
            const float4* yr = reinterpret_cast<const float4*>(yp + (size_t)rimg * IMG + cb);
#pragma unroll
            for (int v = 0; v < 5; v++) {
                const float4 fx = __ldg(xr + v);
                const float4 fy = __ldg(yr + v);
                const float xe[4] = { fx.x, fx.y, fx.z, fx.w };
                const float ye[4] = { fy.x, fy.y, fy.z, fy.w };
#pragma unroll
                for (int e = 0; e < 4; e++) {
                    const int i = 4 * v + e;       // col cb+i; window i in [3,17)
                    if (i >= 3 && i < 17)
                        wsd[i - 3] = pk2(xe[e] + ye[e], xe[e] - ye[e]);
                }
            }
        } else if (COLG && rok) {
#pragma unroll
            for (int m = 0; m < 14; m++) {
                const int c = cb + 3 + m;
                float xv = 0.f, yv = 0.f;
                if ((unsigned)c < IMG) {
                    xv = __ldg(xp + (size_t)rimg * IMG + c);
                    yv = __ldg(yp + (size_t)rimg * IMG + c);
                }
                wsd[m] = pk2(xv + yv, xv - yv);
            }
        } else {
#pragma unroll
            for (int m = 0; m < 14; m++) wsd[m] = 0;
        }

        // MSE: owned local rows only (hi lane of wsd = D)
        if (rr >= mlo && rr < mhi) {
#pragma unroll
            for (int m = 5; m < 9; m++) msep = f2fma(wsd[m], wsd[m], msep);
        }

        // SD conv + store
        {
            u64 o0 = conv11(wsd + 0, G2), o1 = conv11(wsd + 1, G2);
            u64 o2 = conv11(wsd + 2, G2), o3 = conv11(wsd + 3, G2);
            float a0, b0, a1, b1;
            float4* p = reinterpret_cast<float4*>(&Hsd[hb][q * 4]);
            upk(o0, a0, b0); upk(o1, a1, b1);
            p[0] = make_float4(a0, b0, a1, b1);
            upk(o2, a0, b0); upk(o3, a1, b1);
            p[1] = make_float4(a0, b0, a1, b1);
        }
        // square in place, UV conv + store
#pragma unroll
        for (int m = 0; m < 14; m++) wsd[m] = f2mul(wsd[m], wsd[m]);
        {
            u64 o0 = conv11(wsd + 0, G2), o1 = conv11(wsd + 1, G2);
            u64 o2 = conv11(wsd + 2, G2), o3 = conv11(wsd + 3, G2);
            float a0, b0, a1, b1;
            float4* p = reinterpret_cast<float4*>(&Huv[hb][q * 4]);
            upk(o0, a0, b0); upk(o1, a1, b1);
            p[0] = make_float4(a0, b0, a1, b1);
            upk(o2, a0, b0); upk(o3, a1, b1);
            p[1] = make_float4(a0, b0, a1, b1);
        }
    }
    return msep;
}

__device__ __forceinline__ u64 produceDispatch(
    bool colg, bool rowg,
    const float* __restrict__ xp, const float* __restrict__ yp,
    int col0, int tid, int hb0, int rimg0, int nrows, int mlo, int mhi,
    u64 (*Hsd)[HSTRIDE], u64 (*Huv)[HSTRIDE], const u64* G2)
{
    if (colg) {
        if (rowg) return produceRows<true , true >(xp, yp, col0, tid, hb0, rimg0, nrows, mlo, mhi, Hsd, Huv, G2);
        else      return produceRows<true , false>(xp, yp, col0, tid, hb0, rimg0, nrows, mlo, mhi, Hsd, Huv, G2);
    } else {
        if (rowg) return produceRows<false, true >(xp, yp, col0, tid, hb0, rimg0, nrows, mlo, mhi, Hsd, Huv, G2);
        else      return produceRows<false, false>(xp, yp, col0, tid, hb0, rimg0, nrows, mlo, mhi, Hsd, Huv, G2);
    }
}

// ---------------- Phase B consumer: one 64x32 chunk ----------------
__device__ __forceinline__ float consumeChunk(
    int tid, u64 (*Hsd)[HSTRIDE], u64 (*Huv)[HSTRIDE], const u64* G2, u64 MM1)
{
    const int col   = tid & 63;
    const int strip = tid >> 6;
    const int rb    = strip * 8;

    u64 ring[11];
    u64 vsd[8];

    // pass 1: SD stream
#pragma unroll
    for (int k = 0; k < 10; k++) ring[k] = Hsd[rb + k][col];
#pragma unroll
    for (int r = 0; r < 8; r++) {
        ring[(r + 10) % 11] = Hsd[rb + r + 10][col];
        u64 acc = f2mul(G2[5], ring[(r + 5) % 11]);
#pragma unroll
        for (int k = 0; k < 5; k++)
            acc = f2fma(G2[k], f2add(ring[(r + k) % 11], ring[(r + 10 - k) % 11]), acc);
        vsd[r] = acc;
    }

    // pass 2: UV stream + epilogue (x4-scaled: ratio unchanged)
    float ssim_acc = 0.f;
#pragma unroll
    for (int k = 0; k < 10; k++) ring[k] = Huv[rb + k][col];
#pragma unroll
    for (int r = 0; r < 8; r++) {
        ring[(r + 10) % 11] = Huv[rb + r + 10][col];
        u64 acc = f2mul(G2[5], ring[(r + 5) % 11]);
#pragma unroll
        for (int k = 0; k < 5; k++)
            acc = f2fma(G2[k], f2add(ring[(r + k) % 11], ring[(r + 10 - k) % 11]), acc);

        const u64 s2d2 = f2mul(vsd[r], vsd[r]);          // (S^2, D^2)
        const u64 varp = f2fma(s2d2, MM1, acc);          // (varS, varD)
        float S2, D2, varS, varD;
        upk(s2d2, S2, D2);
        upk(varp, varS, varD);
        const float Ap = S2 - D2;            // 4*mu1*mu2
        const float Mp = S2 + D2;            // 2*(mu1^2+mu2^2)
        const float cd = varS - varD;        // 4*sigma12
        const float cs = varS + varD;        // 2*(sigma1^2+sigma2^2)
        const float num = (Ap + C1X2) * (cd + C2X2);
        const float den = (Mp + C1X2) * (cs + C2X2);
        ssim_acc += __fdividef(num, den);
    }
    return ssim_acc;
}

__global__ void __launch_bounds__(NT, 4) ssim_mse_kernel(
    const float* __restrict__ x, const float* __restrict__ y,
    float* __restrict__ out)
{
    __shared__ alignas(16) u64 Hsd[HB][HSTRIDE];
    __shared__ alignas(16) u64 Huv[HB][HSTRIDE];
    __shared__ float red_m[8], red_s[8];

    const int plane = blockIdx.z;
    const int row0  = blockIdx.y * STRIPH;
    const int col0  = blockIdx.x * TW;
    const float* xp = x + (size_t)plane * (IMG * IMG);
    const float* yp = y + (size_t)plane * (IMG * IMG);
    const int tid = threadIdx.x;

    const u64 G2[6] = { pk2(GW[0], GW[0]), pk2(GW[1], GW[1]), pk2(GW[2], GW[2]),
                        pk2(GW[3], GW[3]), pk2(GW[4], GW[4]), pk2(GW[5], GW[5]) };
    const u64 MM1 = pk2(-1.0f, -1.0f);

    const bool colg = (blockIdx.x == 0) || (blockIdx.x == 7);

    u64 msep = 0;
    float ssim_acc = 0.f;

    // chunk 0: fill all 42 buffer rows (image rows row0-5 .. row0+36)
    msep = produceDispatch(colg, blockIdx.y == 0,
                           xp, yp, col0, tid, 0, row0 - 5, HB, 5, HB,
                           Hsd, Huv, G2);
    __syncthreads();
    ssim_acc += consumeChunk(tid, Hsd, Huv, G2, MM1);

#pragma unroll
    for (int c = 1; c < STRIPH / CHUNK; c++) {
        __syncthreads();                       // consume done before copy
        // slide buffer: rows 32..41 -> 0..9
        for (int i = tid; i < 640; i += NT) {
            const int rw = i >> 6, cl = i & 63;
            Hsd[rw][cl] = Hsd[rw + 32][cl];
            Huv[rw][cl] = Huv[rw + 32][cl];
        }
        __syncthreads();                       // copy done before produce overwrites
        const bool rowg = (c == 3) && (blockIdx.y == 3);
        const int  mhi  = (c == 3) ? 27 : 32;  // rows past strip owned by next strip
        msep = f2add(msep,
            produceDispatch(colg, rowg,
                            xp, yp, col0, tid, 10, row0 + 32 * c + 5, CHUNK, 0, mhi,
                            Hsd, Huv, G2));
        __syncthreads();                       // produce done before consume
        ssim_acc += consumeChunk(tid, Hsd, Huv, G2, MM1);
    }

    float mse_lo, mse_acc;
    upk(msep, mse_lo, mse_acc);                // hi lane = sum D^2

    // ---------------- Reduction + fused finalize ----------------
#pragma unroll
    for (int o = 16; o > 0; o >>= 1) {
        mse_acc  += __shfl_down_sync(0xffffffffu, mse_acc,  o);
        ssim_acc += __shfl_down_sync(0xffffffffu, ssim_acc, o);
    }
    const int wid = tid >> 5;
    if ((tid & 31) == 0) { red_m[wid] = mse_acc; red_s[wid] = ssim_acc; }
    __syncthreads();
    if (tid < 32) {
        float m  = (tid < 8) ? red_m[tid] : 0.f;
        float ss = (tid < 8) ? red_s[tid] : 0.f;
#pragma unroll
        for (int o = 4; o > 0; o >>= 1) {
            m  += __shfl_down_sync(0xffffffffu, m,  o);
            ss += __shfl_down_sync(0xffffffffu, ss, o);
        }
        if (tid == 0) {
            atomicAdd(&g_acc[0], (double)m);
            atomicAdd(&g_acc[1], (double)ss);
            __threadfence();
            const unsigned c = atomicAdd(&g_count, 1u);
            if (c == NBLOCKS - 1) {
                __threadfence();
                const double mse  = g_acc[0] / NPIX;
                const double ssim = g_acc[1] / NPIX;
                out[0] = (float)(0.7 * mse + 0.3 * (1.0 - ssim));
                g_acc[0] = 0.0;
                g_acc[1] = 0.0;
                __threadfence();
                g_count = 0u;
            }
        }
    }
}

extern "C" void kernel_launch(void* const* d_in, const int* in_sizes, int n_in,
                              void* d_out, int out_size)
{
    const float* recon = (const float*)d_in[0];
    const float* orig  = (const float*)d_in[1];
    float* out = (float*)d_out;

    dim3 grid(IMG / TW, IMG / STRIPH, NPLANES);   // 8 x 4 x 192 = 6144 blocks
    ssim_mse_kernel<<<grid, NT>>>(recon, orig, out);
}

// round 13
// speedup vs baseline: 1.0393x; 1.0179x over previous
#include <cuda_runtime.h>

#define IMG      512
#define TW       64
#define STRIPH   128
#define CHUNK    32
#define HB       42          // smem buffer rows
#define HSTRIDE  66          // 528B row stride, 16B-aligned float4 stores
#define NT       256
#define NTILES   (8 * 4 * 192)   // 6144 logical tiles
#define NBLK     608             // 152 SMs * 4 resident blocks
#define NPIX     (64.0 * 3.0 * 512.0 * 512.0)

typedef unsigned long long u64;

__device__ constexpr float GW[6] = {
    1.0283886e-3f, 7.5988485e-3f, 3.6000773e-2f, 1.0936073e-1f, 2.1300553e-1f,
    2.6601180e-1f
};

#define C1X2 8.0e-4f     // 2*C1
#define C2X2 7.2e-3f     // 2*C2

__device__ double g_acc[2];
__device__ unsigned int g_count;
__device__ unsigned int g_tile;

// ---------- packed f32x2 helpers ----------
__device__ __forceinline__ u64 pk2(float lo, float hi) {
    u64 r; asm("mov.b64 %0,{%1,%2};" : "=l"(r) : "f"(lo), "f"(hi)); return r;
}
__device__ __forceinline__ void upk(u64 a, float& lo, float& hi) {
    asm("mov.b64 {%0,%1},%2;" : "=f"(lo), "=f"(hi) : "l"(a));
}
__device__ __forceinline__ u64 f2fma(u64 a, u64 b, u64 c) {
    u64 d; asm("fma.rn.f32x2 %0,%1,%2,%3;" : "=l"(d) : "l"(a), "l"(b), "l"(c)); return d;
}
__device__ __forceinline__ u64 f2add(u64 a, u64 b) {
    u64 d; asm("add.rn.f32x2 %0,%1,%2;" : "=l"(d) : "l"(a), "l"(b)); return d;
}
__device__ __forceinline__ u64 f2mul(u64 a, u64 b) {
    u64 d; asm("mul.rn.f32x2 %0,%1,%2;" : "=l"(d) : "l"(a), "l"(b)); return d;
}

// 11-tap symmetric conv on packed pairs
__device__ __forceinline__ u64 conv11(const u64* w, const u64* G2) {
    u64 acc = f2mul(G2[5], w[5]);
#pragma unroll
    for (int k = 0; k < 5; k++)
        acc = f2fma(G2[k], f2add(w[k], w[10 - k]), acc);
    return acc;
}

// ---------------- Phase A producer: nrows H-rows into buffer ----------------
template <bool COLG, bool ROWG>
__device__ __forceinline__ u64 produceRows(
    const float* __restrict__ xp, const float* __restrict__ yp,
    int col0, int tid, int hb0, int rimg0, int nrows, int mlo, int mhi,
    u64 (*Hsd)[HSTRIDE], u64 (*Huv)[HSTRIDE], const u64* G2)
{
    u64 msep = 0;
    for (int s = tid; s < (nrows << 4); s += NT) {
        const int rr = s >> 4;
        const int q  = s & 15;
        const int hb = hb0 + rr;
        const int rimg = rimg0 + rr;
        const int cb   = col0 + q * 4 - 8;   // 16B aligned

        u64 wsd[14];
        bool rok = true, vec = true;
        if (ROWG) { rok = ((unsigned)rimg < IMG); vec = rok; }
        if (COLG) vec = vec && (cb >= 0) && (cb + 20 <= IMG);

        if (vec) {
            const float4* xr = reinterpret_cast<const float4*>(xp + (size_t)rimg * IMG + cb);
            const float4* yr = reinterpret_cast<const float4*>(yp + (size_t)rimg * IMG + cb);
#pragma unroll
            for (int v = 0; v < 5; v++) {
                const float4 fx = __ldg(xr + v);
                const float4 fy = __ldg(yr + v);
                const float xe[4] = { fx.x, fx.y, fx.z, fx.w };
                const float ye[4] = { fy.x, fy.y, fy.z, fy.w };
#pragma unroll
                for (int e = 0; e < 4; e++) {
                    const int i = 4 * v + e;       // col cb+i; window i in [3,17)
                    if (i >= 3 && i < 17)
                        wsd[i - 3] = pk2(xe[e] + ye[e], xe[e] - ye[e]);
                }
            }
        } else if (COLG && rok) {
#pragma unroll
            for (int m = 0; m < 14; m++) {
                const int c = cb + 3 + m;
                float xv = 0.f, yv = 0.f;
                if ((unsigned)c < IMG) {
                    xv = __ldg(xp + (size_t)rimg * IMG + c);
                    yv = __ldg(yp + (size_t)rimg * IMG + c);
                }
                wsd[m] = pk2(xv + yv, xv - yv);
            }
        } else {
#pragma unroll
            for (int m = 0; m < 14; m++) wsd[m] = 0;
        }

        // MSE: owned local rows only (hi lane of wsd = D)
        if (rr >= mlo && rr < mhi) {
#pragma unroll
            for (int m = 5; m < 9; m++) msep = f2fma(wsd[m], wsd[m], msep);
        }

        // SD conv + store
        {
            u64 o0 = conv11(wsd + 0, G2), o1 = conv11(wsd + 1, G2);
            u64 o2 = conv11(wsd + 2, G2), o3 = conv11(wsd + 3, G2);
            float a0, b0, a1, b1;
            float4* p = reinterpret_cast<float4*>(&Hsd[hb][q * 4]);
            upk(o0, a0, b0); upk(o1, a1, b1);
            p[0] = make_float4(a0, b0, a1, b1);
            upk(o2, a0, b0); upk(o3, a1, b1);
            p[1] = make_float4(a0, b0, a1, b1);
        }
        // square in place, UV conv + store
#pragma unroll
        for (int m = 0; m < 14; m++) wsd[m] = f2mul(wsd[m], wsd[m]);
        {
            u64 o0 = conv11(wsd + 0, G2), o1 = conv11(wsd + 1, G2);
            u64 o2 = conv11(wsd + 2, G2), o3 = conv11(wsd + 3, G2);
            float a0, b0, a1, b1;
            float4* p = reinterpret_cast<float4*>(&Huv[hb][q * 4]);
            upk(o0, a0, b0); upk(o1, a1, b1);
            p[0] = make_float4(a0, b0, a1, b1);
            upk(o2, a0, b0); upk(o3, a1, b1);
            p[1] = make_float4(a0, b0, a1, b1);
        }
    }
    return msep;
}

__device__ __forceinline__ u64 produceDispatch(
    bool colg, bool rowg,
    const float* __restrict__ xp, const float* __restrict__ yp,
    int col0, int tid, int hb0, int rimg0, int nrows, int mlo, int mhi,
    u64 (*Hsd)[HSTRIDE], u64 (*Huv)[HSTRIDE], const u64* G2)
{
    if (colg) {
        if (rowg) return produceRows<true , true >(xp, yp, col0, tid, hb0, rimg0, nrows, mlo, mhi, Hsd, Huv, G2);
        else      return produceRows<true , false>(xp, yp, col0, tid, hb0, rimg0, nrows, mlo, mhi, Hsd, Huv, G2);
    } else {
        if (rowg) return produceRows<false, true >(xp, yp, col0, tid, hb0, rimg0, nrows, mlo, mhi, Hsd, Huv, G2);
        else      return produceRows<false, false>(xp, yp, col0, tid, hb0, rimg0, nrows, mlo, mhi, Hsd, Huv, G2);
    }
}

// ---------------- Phase B consumer: one 64x32 chunk ----------------
__device__ __forceinline__ float consumeChunk(
    int tid, u64 (*Hsd)[HSTRIDE], u64 (*Huv)[HSTRIDE], const u64* G2, u64 MM1)
{
    const int col   = tid & 63;
    const int strip = tid >> 6;
    const int rb    = strip * 8;

    u64 ring[11];
    u64 vsd[8];

    // pass 1: SD stream
#pragma unroll
    for (int k = 0; k < 10; k++) ring[k] = Hsd[rb + k][col];
#pragma unroll
    for (int r = 0; r < 8; r++) {
        ring[(r + 10) % 11] = Hsd[rb + r + 10][col];
        u64 acc = f2mul(G2[5], ring[(r + 5) % 11]);
#pragma unroll
        for (int k = 0; k < 5; k++)
            acc = f2fma(G2[k], f2add(ring[(r + k) % 11], ring[(r + 10 - k) % 11]), acc);
        vsd[r] = acc;
    }

    // pass 2: UV stream + epilogue (x4-scaled: ratio unchanged)
    float ssim_acc = 0.f;
#pragma unroll
    for (int k = 0; k < 10; k++) ring[k] = Huv[rb + k][col];
#pragma unroll
    for (int r = 0; r < 8; r++) {
        ring[(r + 10) % 11] = Huv[rb + r + 10][col];
        u64 acc = f2mul(G2[5], ring[(r + 5) % 11]);
#pragma unroll
        for (int k = 0; k < 5; k++)
            acc = f2fma(G2[k], f2add(ring[(r + k) % 11], ring[(r + 10 - k) % 11]), acc);

        const u64 s2d2 = f2mul(vsd[r], vsd[r]);          // (S^2, D^2)
        const u64 varp = f2fma(s2d2, MM1, acc);          // (varS, varD)
        float S2, D2, varS, varD;
        upk(s2d2, S2, D2);
        upk(varp, varS, varD);
        const float Ap = S2 - D2;            // 4*mu1*mu2
        const float Mp = S2 + D2;            // 2*(mu1^2+mu2^2)
        const float cd = varS - varD;        // 4*sigma12
        const float cs = varS + varD;        // 2*(sigma1^2+sigma2^2)
        const float num = (Ap + C1X2) * (cd + C2X2);
        const float den = (Mp + C1X2) * (cs + C2X2);
        ssim_acc += __fdividef(num, den);
    }
    return ssim_acc;
}

template <bool COLG>
__device__ __forceinline__ void runStrip(
    const float* __restrict__ xp, const float* __restrict__ yp,
    int row0, int col0, int tid, int by,
    u64 (*Hsd)[HSTRIDE], u64 (*Huv)[HSTRIDE],
    const u64* G2, u64 MM1, u64& msep, float& ssim_acc)
{
    // chunk 0: fill all 42 buffer rows (image rows row0-5 .. row0+36)
    msep = f2add(msep, produceDispatch(COLG, by == 0,
                       xp, yp, col0, tid, 0, row0 - 5, HB, 5, HB, Hsd, Huv, G2));
    __syncthreads();
    ssim_acc += consumeChunk(tid, Hsd, Huv, G2, MM1);

#pragma unroll
    for (int c = 1; c < STRIPH / CHUNK; c++) {
        __syncthreads();                       // consume done before copy
        // slide buffer: rows 32..41 -> 0..9
        for (int i = tid; i < 640; i += NT) {
            const int rw = i >> 6, cl = i & 63;
            Hsd[rw][cl] = Hsd[rw + 32][cl];
            Huv[rw][cl] = Huv[rw + 32][cl];
        }
        __syncthreads();                       // copy done before produce overwrites
        const bool rowg = (c == 3) && (by == 3);
        const int  mhi  = (c == 3) ? 27 : 32;  // rows past strip owned by next strip
        msep = f2add(msep,
            produceDispatch(COLG, rowg,
                            xp, yp, col0, tid, 10, row0 + 32 * c + 5, CHUNK, 0, mhi,
                            Hsd, Huv, G2));
        __syncthreads();                       // produce done before consume
        ssim_acc += consumeChunk(tid, Hsd, Huv, G2, MM1);
    }
}

__global__ void __launch_bounds__(NT, 4) ssim_mse_kernel(
    const float* __restrict__ x, const float* __restrict__ y,
    float* __restrict__ out)
{
    __shared__ alignas(16) u64 Hsd[HB][HSTRIDE];
    __shared__ alignas(16) u64 Huv[HB][HSTRIDE];
    __shared__ float red_m[8], red_s[8];
    __shared__ unsigned int cur;

    const int tid = threadIdx.x;

    const u64 G2[6] = { pk2(GW[0], GW[0]), pk2(GW[1], GW[1]), pk2(GW[2], GW[2]),
                        pk2(GW[3], GW[3]), pk2(GW[4], GW[4]), pk2(GW[5], GW[5]) };
    const u64 MM1 = pk2(-1.0f, -1.0f);

    u64 msep = 0;
    float ssim_acc = 0.f;

    // ---------------- persistent tile loop (dynamic work-stealing) ----------------
    while (true) {
        if (tid == 0) cur = atomicAdd(&g_tile, 1u);
        __syncthreads();                       // broadcast tile; also orders prior
                                               // consume-reads before next produce-writes
        const unsigned t = cur;
        if (t >= NTILES) break;

        const int bx    = t & 7;
        const int by    = (t >> 3) & 3;
        const int plane = t >> 5;
        const int row0  = by * STRIPH;
        const int col0  = bx * TW;
        const float* xp = x + (size_t)plane * (IMG * IMG);
        const float* yp = y + (size_t)plane * (IMG * IMG);

        if (bx == 0 || bx == 7)
            runStrip<true >(xp, yp, row0, col0, tid, by, Hsd, Huv, G2, MM1, msep, ssim_acc);
        else
            runStrip<false>(xp, yp, row0, col0, tid, by, Hsd, Huv, G2, MM1, msep, ssim_acc);
    }

    float mse_lo, mse_acc;
    upk(msep, mse_lo, mse_acc);                // hi lane = sum D^2

    // ---------------- Reduction + fused finalize + counter reset ----------------
#pragma unroll
    for (int o = 16; o > 0; o >>= 1) {
        mse_acc  += __shfl_down_sync(0xffffffffu, mse_acc,  o);
        ssim_acc += __shfl_down_sync(0xffffffffu, ssim_acc, o);
    }
    const int wid = tid >> 5;
    if ((tid & 31) == 0) { red_m[wid] = mse_acc; red_s[wid] = ssim_acc; }
    __syncthreads();
    if (tid < 32) {
        float m  = (tid < 8) ? red_m[tid] : 0.f;
        float ss = (tid < 8) ? red_s[tid] : 0.f;
#pragma unroll
        for (int o = 4; o > 0; o >>= 1) {
            m  += __shfl_down_sync(0xffffffffu, m,  o);
            ss += __shfl_down_sync(0xffffffffu, ss, o);
        }
        if (tid == 0) {
            atomicAdd(&g_acc[0], (double)m);
            atomicAdd(&g_acc[1], (double)ss);
            __threadfence();
            const unsigned c = atomicAdd(&g_count, 1u);
            if (c == NBLK - 1) {               // last block: finalize + reset
                __threadfence();
                const double mse  = g_acc[0] / NPIX;
                const double ssim = g_acc[1] / NPIX;
                out[0] = (float)(0.7 * mse + 0.3 * (1.0 - ssim));
                g_acc[0] = 0.0;
                g_acc[1] = 0.0;
                g_tile   = 0u;
                __threadfence();
                g_count = 0u;
            }
        }
    }
}

extern "C" void kernel_launch(void* const* d_in, const int* in_sizes, int n_in,
                              void* d_out, int out_size)
{
    const float* recon = (const float*)d_in[0];
    const float* orig  = (const float*)d_in[1];
    float* out = (float*)d_out;

    ssim_mse_kernel<<<NBLK, NT>>>(recon, orig, out);   // 608 persistent blocks
}